// round 17
// baseline (speedup 1.0000x reference)
#include <cuda_runtime.h>
#include <math.h>

#define NMAX 100000

__device__ float    g_diag[NMAX];
__device__ unsigned g_deg[NMAX];

// ---------------------------------------------------------------------------
// K1 (heterogeneous): diag-GEMV blocks + deg-atomic blocks (NO copy here).
//   diag block: 8 warps x 2 rows = 16 rows of x (DRAM-bound)
//   deg  block: 256 threads x int4 = 1024 edges, cols only (LTS-atomic)
//   Pattern (when GDIAG == 2*GDEG): bid%3<2 -> diag, bid%3==2 -> deg.
// ---------------------------------------------------------------------------
__global__ void __launch_bounds__(256)
k_fused(const float* __restrict__ x,
        const float* __restrict__ w,
        const float* __restrict__ b,
        int n,
        const int* __restrict__ ei,
        int E, int E4,
        int GDIAG, int GDEG, int interleave) {
    int bid = blockIdx.x;
    int is_diag, sub;
    if (interleave) {
        int g3 = bid / 3, r3 = bid - g3 * 3;
        if (bid < 3 * GDEG) {
            if (r3 < 2) { is_diag = 1; sub = g3 * 2 + r3; }
            else        { is_diag = 0; sub = g3; }
        } else {
            is_diag = 1; sub = 2 * GDEG + (bid - 3 * GDEG);
        }
    } else {
        if (bid < GDIAG) { is_diag = 1; sub = bid; }
        else             { is_diag = 0; sub = bid - GDIAG; }
    }

    if (is_diag) {
        // ---------------- diag portion: 2 rows per warp ----------------
        if (sub >= GDIAG) return;
        __shared__ float4 ws[64];
        int t = threadIdx.x;
        if (t < 64) ws[t] = ((const float4*)w)[t];
        __syncthreads();

        int lane = t & 31;
        int warp = sub * 8 + (t >> 5);
        int row0 = warp << 1;
        if (row0 >= n) return;
        bool has1 = (row0 + 1) < n;

        const float4* xr0 = (const float4*)(x + (size_t)row0 * 256);
        const float4* xr1 = (const float4*)(x + (size_t)(row0 + 1) * 256);

        float4 a0 = xr0[lane];
        float4 a1 = xr0[lane + 32];
        float4 c0, c1;
        if (has1) { c0 = xr1[lane]; c1 = xr1[lane + 32]; }
        else      { c0 = make_float4(0,0,0,0); c1 = c0; }

        float4 w0 = ws[lane];
        float4 w1 = ws[lane + 32];

        float s0 = a0.x*w0.x + a0.y*w0.y + a0.z*w0.z + a0.w*w0.w
                 + a1.x*w1.x + a1.y*w1.y + a1.z*w1.z + a1.w*w1.w;
        float s1 = c0.x*w0.x + c0.y*w0.y + c0.z*w0.z + c0.w*w0.w
                 + c1.x*w1.x + c1.y*w1.y + c1.z*w1.z + c1.w*w1.w;

#pragma unroll
        for (int o = 16; o; o >>= 1) {
            s0 += __shfl_xor_sync(0xffffffffu, s0, o);
            s1 += __shfl_xor_sync(0xffffffffu, s1, o);
        }
        if (lane == 0) {
            float bb = b[0];
            g_diag[row0] = 1.0f / (1.0f + expf(-(s0 + bb)));
            if (has1) g_diag[row0 + 1] = 1.0f / (1.0f + expf(-(s1 + bb)));
        }
    } else {
        // ---------------- deg portion: cols only, atomics ----------------
        int i = sub * 256 + threadIdx.x;
        if (i >= E4) return;
        int4 c = ((const int4*)(ei + E))[i];
        if ((unsigned)c.x < NMAX) atomicAdd(&g_deg[c.x], 1u);
        if ((unsigned)c.y < NMAX) atomicAdd(&g_deg[c.y], 1u);
        if ((unsigned)c.z < NMAX) atomicAdd(&g_deg[c.z], 1u);
        if ((unsigned)c.w < NMAX) atomicAdd(&g_deg[c.w], 1u);
    }
}

// ---------------------------------------------------------------------------
// K2 (heterogeneous): val blocks (gather-bound) + copy blocks (DRAM streaming).
//   val block: 256 threads x 4 edges (identical to proven 27.3us k_val)
//   copy block: 256 threads x 5 int4-groups -> idx->float copy
//   Pattern (5 val : 1 copy): bid%6==5 -> copy.
// ---------------------------------------------------------------------------
__global__ void __launch_bounds__(256)
k_val2(const int* __restrict__ ei,
       const float* __restrict__ attr,
       float* __restrict__ out_idx,
       float* __restrict__ outv,
       int E4, int E,
       int GVAL, int GCOPY, int CL, int interleave) {
    int bid = blockIdx.x;
    int is_copy, sub;
    if (interleave) {              // GVAL == 5*GCOPY exactly
        int g6 = bid / 6, r6 = bid - g6 * 6;
        if (r6 == 5) { is_copy = 1; sub = g6; }
        else         { is_copy = 0; sub = g6 * 5 + r6; }
    } else {
        if (bid < GVAL) { is_copy = 0; sub = bid; }
        else            { is_copy = 1; sub = bid - GVAL; }
    }

    if (!is_copy) {
        // ---------------- val portion ----------------
        int i = sub * 256 + threadIdx.x;
        if (i >= E4) return;

        int4 r = ((const int4*)ei)[i];
        int4 c = ((const int4*)(ei + E))[i];
        float4 a = ((const float4*)attr)[i];

        unsigned u0 = ((unsigned)r.x < NMAX) ? g_deg[r.x] : 1u;
        unsigned u1 = ((unsigned)r.y < NMAX) ? g_deg[r.y] : 1u;
        unsigned u2 = ((unsigned)r.z < NMAX) ? g_deg[r.z] : 1u;
        unsigned u3 = ((unsigned)r.w < NMAX) ? g_deg[r.w] : 1u;
        float g0 = ((unsigned)c.x < NMAX) ? g_diag[c.x] : 0.0f;
        float g1 = ((unsigned)c.y < NMAX) ? g_diag[c.y] : 0.0f;
        float g2 = ((unsigned)c.z < NMAX) ? g_diag[c.z] : 0.0f;
        float g3 = ((unsigned)c.w < NMAX) ? g_diag[c.w] : 0.0f;

        float4 v;
        v.x = a.x * g0 * __frcp_rn(__uint2float_rn(u0));
        v.y = a.y * g1 * __frcp_rn(__uint2float_rn(u1));
        v.z = a.z * g2 * __frcp_rn(__uint2float_rn(u2));
        v.w = a.w * g3 * __frcp_rn(__uint2float_rn(u3));
        ((float4*)outv)[i] = v;
    } else {
        // ---------------- copy portion: CL int4-groups per thread --------
        int base = sub * 256 * CL;
        for (int k = 0; k < CL; k++) {
            int i = base + k * 256 + threadIdx.x;
            if (i >= E4) break;
            int4 r = ((const int4*)ei)[i];
            int4 c = ((const int4*)(ei + E))[i];
            ((float4*)out_idx)[i] =
                make_float4((float)r.x, (float)r.y, (float)r.z, (float)r.w);
            ((float4*)(out_idx + E))[i] =
                make_float4((float)c.x, (float)c.y, (float)c.z, (float)c.w);
        }
    }
}

// ---------------------------------------------------------------------------
static void* g_deg_addr = nullptr;

extern "C" void kernel_launch(void* const* d_in, const int* in_sizes, int n_in,
                              void* d_out, int out_size) {
    const float* x    = (const float*)d_in[0];
    const int*   ei   = (const int*)d_in[1];     // int32 (2, E)
    const float* attr = (const float*)d_in[2];
    const float* w    = (const float*)d_in[3];
    const float* b    = (const float*)d_in[4];

    const int E  = in_sizes[2];
    const int Dd = in_sizes[3];
    const int n  = in_sizes[0] / Dd;

    if (!g_deg_addr) cudaGetSymbolAddress(&g_deg_addr, g_deg);

    float* out = (float*)d_out;
    float* out_vals;
    int write_idx;
    if (out_size >= 3 * E) {      // [edge_index(2E) | vals(E)] as float32
        write_idx = 1;
        out_vals = out + 2 * (size_t)E;
    } else {
        write_idx = 0;
        out_vals = out;
    }

    const int T = 256;
    const int E4 = E >> 2;

    // --- K1 grid: diag + deg ---
    const int GDIAG = (n + 15) / 16;           // 16 rows per diag block
    const int GDEG  = (E4 + T - 1) / T;        // 1024 edges per deg block
    const int inter1 = (GDIAG == 2 * GDEG);

    // --- K2 grid: val + copy ---
    const int GVAL = (E4 + T - 1) / T;
    const int CL = 5;                           // int4-groups per copy thread
    const int GCOPY = write_idx ? (E4 + T * CL - 1) / (T * CL) : 0;
    const int inter2 = (write_idx && GVAL == 5 * GCOPY);

    // zero degree counters via graph memset node
    cudaMemsetAsync(g_deg_addr, 0, (size_t)n * sizeof(unsigned), 0);

    k_fused<<<GDIAG + GDEG, T>>>(x, w, b, n, ei, E, E4,
                                 GDIAG, GDEG, inter1);
    k_val2<<<GVAL + GCOPY, T>>>(ei, attr, out, out_vals, E4, E,
                                GVAL, GCOPY, CL, inter2);
}